// round 16
// baseline (speedup 1.0000x reference)
#include <cuda_runtime.h>
#include <cuda_fp16.h>
#include <stdint.h>
#include <math.h>

#define BATCH 64
#define SEQ   256
#define DIM   1024
#define BETA_C 0.75f
#define TEMP_C 0.1f

// ---- GEMM tiling ----
#define BM 128
#define BN 128
#define BK 32
#define NKT (DIM / BK)              // 32 k-chunks
#define STAGES 4
#define STAGE_BYTES 16384           // A 8KB + B 8KB (halves)
#define SMEM_TOTAL (STAGES * STAGE_BYTES)   // 64 KB

// ---------------- device scratch ----------------
__device__ float g_part[2][4][BATCH][DIM];   // split-K partials: [iCi|co][ks][b][d]
__device__ float g_simn[BATCH * SEQ];
__device__ float g_sig[BATCH * SEQ];
__device__ float g_Wt[DIM * DIM];
__device__ __half g_Ah[BATCH * SEQ * DIM];   // text_enc in fp16
__device__ __half g_Wh[DIM * DIM];           // weight in fp16

// ================ P1: prepW (1024 x 128thr) + smallgemm-iCi (256 x 128thr) ======
__global__ __launch_bounds__(128) void k_p1(
    const float* __restrict__ W,
    const float* __restrict__ Cinv,
    const int* __restrict__ prompt_ids,
    const int* __restrict__ concept_indices,
    const uint8_t* __restrict__ initted,
    const float* __restrict__ ema_table,
    const float* __restrict__ text_enc) {
    __shared__ __align__(16) char sbuf[4352];
    const int bid = blockIdx.x;
    const int tid = threadIdx.x;

    if (bid < 1024) {
        // ---- transpose + fp16 convert; 128 threads, 8 rows each ----
        float (*t)[33] = (float(*)[33])sbuf;
        int bx = bid & 31, by = bid >> 5;
        int tx = tid & 31, ty = tid >> 5;     // ty 0..3
        int x = bx * 32 + tx;
        int y0 = by * 32;
#pragma unroll
        for (int j = 0; j < 32; j += 4) {
            float v = W[(size_t)(y0 + ty + j) * DIM + x];
            t[ty + j][tx] = v;
            g_Wh[(size_t)(y0 + ty + j) * DIM + x] = __float2half_rn(v);
        }
        __syncthreads();
        int x2 = by * 32 + tx;
        int y2 = bx * 32;
#pragma unroll
        for (int j = 0; j < 32; j += 4)
            g_Wt[(size_t)(y2 + ty + j) * DIM + x2] = t[tx][ty + j];
    } else {
        // ---- smallgemm iCi partials (R9-exact body); q -> (dblk, bblk, ks) ----
        const float** srcp = (const float**)sbuf;
        float (*ish)[128] = (float(*)[128])(sbuf + 64);
        int q = bid - 1024;                   // 0..255
        const int d = (q & 7) * 128 + tid;
        const int b0 = ((q >> 3) & 7) * 8;
        const int ks = q >> 6;                // 0..3
        if (tid < 8) {
            int b = b0 + tid;
            int pid = prompt_ids[b];
            int ci = concept_indices[b];
            bool init = initted[pid] != 0;
            srcp[tid] = init ? (ema_table + (size_t)pid * DIM)
                             : (text_enc + ((size_t)b * SEQ + ci) * DIM);
        }
        __syncthreads();

        float acc[8];
#pragma unroll
        for (int r = 0; r < 8; r++) acc[r] = 0.0f;
        const int kbase = ks * 256;
#pragma unroll
        for (int kh = 0; kh < 2; kh++) {
            int k0 = kbase + kh * 128;
#pragma unroll
            for (int r = 0; r < 8; r++) ish[r][tid] = srcp[r][k0 + tid];
            __syncthreads();
#pragma unroll 4
            for (int kk = 0; kk < 128; kk++) {
                float m = Cinv[(size_t)(k0 + kk) * DIM + d];
#pragma unroll
                for (int r = 0; r < 8; r++) acc[r] += ish[r][kk] * m;
            }
            __syncthreads();
        }
#pragma unroll
        for (int r = 0; r < 8; r++) g_part[0][ks][b0 + r][d] = acc[r];
    }
}

// ================ P2: simE (2048 x 256thr) + smallgemm-co (128 x 256thr) ========
__global__ __launch_bounds__(256) void k_p2(
    const int* __restrict__ prompt_ids,
    const int* __restrict__ concept_indices,
    const uint8_t* __restrict__ initted,
    const float* __restrict__ ema_table,
    const float* __restrict__ text_enc) {
    __shared__ __align__(16) char sbuf[4480];
    const int bid = blockIdx.x;
    const int tid = threadIdx.x;

    if (bid < 2048) {
        // ---- simE (R9-exact) ----
        float* sm_iCi = (float*)sbuf;                 // 4096 B
        float* red = (float*)(sbuf + 4096);           // 32 B
        float* sE = (float*)(sbuf + 4128);
        const int m0 = bid * 8;
        const int b = bid >> 5;

        int pid = prompt_ids[b];
        int ci = concept_indices[b];
        bool init = initted[pid] != 0;
        const float* isrc = init ? (ema_table + (size_t)pid * DIM)
                                 : (text_enc + ((size_t)b * SEQ + ci) * DIM);

        float s = 0.0f;
        for (int d = tid; d < DIM; d += 256) {
            float v = g_part[0][0][b][d] + g_part[0][1][b][d] +
                      g_part[0][2][b][d] + g_part[0][3][b][d];
            sm_iCi[d] = v;
            s += v * isrc[d];
        }
#pragma unroll
        for (int o = 16; o; o >>= 1) s += __shfl_xor_sync(0xffffffffu, s, o);
        if ((tid & 31) == 0) red[tid >> 5] = s;
        __syncthreads();
        if (tid == 0) {
            float t = 0.0f;
#pragma unroll
            for (int w = 0; w < 8; w++) t += red[w];
            *sE = t;
        }
        __syncthreads();

        const int wr = tid >> 5, lane = tid & 31;
        const int m = m0 + wr;
        const float4* x = (const float4*)(text_enc + (size_t)m * DIM);
        const float4* c4 = (const float4*)sm_iCi;
        __half* arow = g_Ah + (size_t)m * DIM;
        float dot = 0.0f;
#pragma unroll
        for (int it = 0; it < 8; it++) {
            int idx = it * 32 + lane;
            float4 xv = x[idx];
            float4 cv = c4[idx];
            dot += xv.x * cv.x + xv.y * cv.y + xv.z * cv.z + xv.w * cv.w;
            __half2 h0 = __floats2half2_rn(xv.x, xv.y);
            __half2 h1 = __floats2half2_rn(xv.z, xv.w);
            uint2 h;
            h.x = *(uint32_t*)&h0;
            h.y = *(uint32_t*)&h1;
            *(uint2*)(arow + idx * 4) = h;
        }
#pragma unroll
        for (int o = 16; o; o >>= 1) dot += __shfl_xor_sync(0xffffffffu, dot, o);
        if (lane == 0) {
            float simn = dot / *sE;
            g_simn[m] = simn;
            g_sig[m] = 1.0f / (1.0f + expf(-(simn - BETA_C) / TEMP_C));
        }
    } else {
        // ---- smallgemm co partials; 256 threads cover 256 d-columns ----
        const float** srcp = (const float**)sbuf;
        float (*ish)[128] = (float(*)[128])(sbuf + 64);
        int q = bid - 2048;                   // 0..127
        const int d = (q & 3) * 256 + tid;
        const int b0 = ((q >> 2) & 7) * 8;
        const int ks = q >> 5;                // 0..3
        if (tid < 8) {
            int b = b0 + tid;
            int pid = prompt_ids[b];
            int ci = concept_indices[b];
            bool init = initted[pid] != 0;
            srcp[tid] = init ? (ema_table + (size_t)pid * DIM)
                             : (text_enc + ((size_t)b * SEQ + ci) * DIM);
        }
        __syncthreads();

        float acc[8];
#pragma unroll
        for (int r = 0; r < 8; r++) acc[r] = 0.0f;
        const int kbase = ks * 256;
#pragma unroll
        for (int kh = 0; kh < 2; kh++) {
            int k0 = kbase + kh * 128;
            // 256 threads load 8x128 slice: 4 elems each
#pragma unroll
            for (int u = 0; u < 4; u++) {
                int e = tid + u * 256;
                ish[e >> 7][e & 127] = srcp[e >> 7][k0 + (e & 127)];
            }
            __syncthreads();
#pragma unroll 4
            for (int kk = 0; kk < 128; kk++) {
                float m = g_Wt[(size_t)(k0 + kk) * DIM + d];
#pragma unroll
                for (int r = 0; r < 8; r++) acc[r] += ish[r][kk] * m;
            }
            __syncthreads();
        }
#pragma unroll
        for (int r = 0; r < 8; r++) g_part[1][ks][b0 + r][d] = acc[r];
    }
}

// ---------------- PTX helpers ----------------
__device__ __forceinline__ uint32_t smem_u32(const void* p) {
    uint32_t a;
    asm("{ .reg .u64 t; cvta.to.shared.u64 t, %1; cvt.u32.u64 %0, t; }" : "=r"(a) : "l"(p));
    return a;
}
__device__ __forceinline__ void cp16(uint32_t dst, const void* src) {
    asm volatile("cp.async.cg.shared.global [%0], [%1], 16;" :: "r"(dst), "l"(src) : "memory");
}
#define CP_COMMIT() asm volatile("cp.async.commit_group;" ::: "memory")
#define CP_WAIT2()  asm volatile("cp.async.wait_group 2;" ::: "memory")
__device__ __forceinline__ uint4 ldsm4(uint32_t addr) {
    uint4 v;
    asm volatile("ldmatrix.sync.aligned.m8n8.x4.shared.b16 {%0,%1,%2,%3}, [%4];"
                 : "=r"(v.x), "=r"(v.y), "=r"(v.z), "=r"(v.w) : "r"(addr));
    return v;
}
__device__ __forceinline__ void mma_f16(float* c, const uint4& a, uint32_t b0, uint32_t b1) {
    asm volatile(
        "mma.sync.aligned.m16n8k16.row.col.f32.f16.f16.f32 "
        "{%0,%1,%2,%3}, {%4,%5,%6,%7}, {%8,%9}, {%0,%1,%2,%3};"
        : "+f"(c[0]), "+f"(c[1]), "+f"(c[2]), "+f"(c[3])
        : "r"(a.x), "r"(a.y), "r"(a.z), "r"(a.w), "r"(b0), "r"(b1));
}
// physical byte offset of (row, 16B-chunk c) in an 8KB half-tile [128 rows x 64B], swizzled
__device__ __forceinline__ uint32_t phys(int r, int c) {
    uint32_t line = r >> 1;
    uint32_t u = ((r & 1) << 2) | c;
    return line * 128 + ((u ^ (line & 7)) << 4);
}

// ---------------- K3: fp16 cp.async + ldmatrix GEMM + fused epilogue (R9 exact) ----
__global__ __launch_bounds__(256, 2) void k_main(
    const int* __restrict__ prompt_ids,
    const uint8_t* __restrict__ initted,
    const float* __restrict__ outputs_table,  // [512][256][1024]
    float* __restrict__ out) {
    extern __shared__ char smem[];
    const uint32_t sb = smem_u32(smem);

    const int tid = threadIdx.x;
    const int wid = tid >> 5, lane = tid & 31;
    const int wm = wid & 1, wn = wid >> 1;     // warp tile rows 64*wm, cols 32*wn
    const int m0 = blockIdx.y * BM;
    const int n0 = blockIdx.x * BN;

    // ---- producer mapping: 2 A chunks + 2 B chunks per thread per stage ----
    const int chA0 = tid, chA1 = tid + 256;    // 0..511
    const int rA0 = chA0 >> 2, cA0 = chA0 & 3;
    const int rA1 = chA1 >> 2, cA1 = chA1 & 3;
    const __half* srcA0 = g_Ah + (size_t)(m0 + rA0) * DIM + cA0 * 8;
    const __half* srcA1 = g_Ah + (size_t)(m0 + rA1) * DIM + cA1 * 8;
    const __half* srcB0 = g_Wh + (size_t)(n0 + rA0) * DIM + cA0 * 8;
    const __half* srcB1 = g_Wh + (size_t)(n0 + rA1) * DIM + cA1 * 8;
    const uint32_t dA0 = phys(rA0, cA0), dA1 = phys(rA1, cA1);
    const uint32_t dB0 = 8192 + dA0, dB1 = 8192 + dA1;

    // ---- consumer ldmatrix offsets ----
    const int lane15 = lane & 15, lanehi = lane >> 4;
    uint32_t offA[4][2], offB[2][2];
#pragma unroll
    for (int i = 0; i < 4; i++)
#pragma unroll
        for (int ks = 0; ks < 2; ks++)
            offA[i][ks] = phys(wm * 64 + i * 16 + lane15, ks * 2 + lanehi);
#pragma unroll
    for (int j2 = 0; j2 < 2; j2++)
#pragma unroll
        for (int ks = 0; ks < 2; ks++)
            offB[j2][ks] = 8192 + phys(wn * 32 + j2 * 16 + lane15, ks * 2 + lanehi);

    float acc[4][4][4];
#pragma unroll
    for (int i = 0; i < 4; i++)
#pragma unroll
        for (int j = 0; j < 4; j++)
#pragma unroll
            for (int r = 0; r < 4; r++) acc[i][j][r] = 0.0f;

    // ---- prologue: issue stages 0..2 ----
#pragma unroll
    for (int s = 0; s < 3; s++) {
        uint32_t base = sb + s * STAGE_BYTES;
        int ko = s * BK;
        cp16(base + dA0, srcA0 + ko);
        cp16(base + dA1, srcA1 + ko);
        cp16(base + dB0, srcB0 + ko);
        cp16(base + dB1, srcB1 + ko);
        CP_COMMIT();
    }

    for (int kt = 0; kt < NKT; kt++) {
        CP_WAIT2();
        __syncthreads();
        uint32_t base = sb + (kt & (STAGES - 1)) * STAGE_BYTES;
#pragma unroll
        for (int ks = 0; ks < 2; ks++) {
            uint4 af[4], bf[2];
#pragma unroll
            for (int i = 0; i < 4; i++) af[i] = ldsm4(base + offA[i][ks]);
#pragma unroll
            for (int j2 = 0; j2 < 2; j2++) bf[j2] = ldsm4(base + offB[j2][ks]);
#pragma unroll
            for (int i = 0; i < 4; i++) {
                mma_f16(acc[i][0], af[i], bf[0].x, bf[0].z);
                mma_f16(acc[i][1], af[i], bf[0].y, bf[0].w);
                mma_f16(acc[i][2], af[i], bf[1].x, bf[1].z);
                mma_f16(acc[i][3], af[i], bf[1].y, bf[1].w);
            }
        }
        if (kt + 3 < NKT) {
            uint32_t nb = sb + ((kt + 3) & (STAGES - 1)) * STAGE_BYTES;
            int ko = (kt + 3) * BK;
            cp16(nb + dA0, srcA0 + ko);
            cp16(nb + dA1, srcA1 + ko);
            cp16(nb + dB0, srcB0 + ko);
            cp16(nb + dB1, srcB1 + ko);
        }
        CP_COMMIT();
    }

    // ---------------- fused epilogue ----------------
    const int b = m0 >> 8;
    const int pid = prompt_ids[b];
    const bool init = initted[pid] != 0;

    float2 co2[4];
#pragma unroll
    for (int j = 0; j < 4; j++) {
        int col = n0 + wn * 32 + j * 8 + (lane & 3) * 2;
        float2 v = *(const float2*)&g_part[1][0][b][col];
        float2 v1 = *(const float2*)&g_part[1][1][b][col];
        float2 v2 = *(const float2*)&g_part[1][2][b][col];
        float2 v3 = *(const float2*)&g_part[1][3][b][col];
        co2[j] = make_float2(v.x + v1.x + v2.x + v3.x, v.y + v1.y + v2.y + v3.y);
    }

#pragma unroll
    for (int i = 0; i < 4; i++) {
        int gr0 = m0 + wm * 64 + i * 16 + (lane >> 2);
        int gr1 = gr0 + 8;
        float simn0 = g_simn[gr0], sig0 = g_sig[gr0];
        float simn1 = g_simn[gr1], sig1 = g_sig[gr1];
        const float* ot0 = outputs_table + ((size_t)pid * SEQ + (gr0 & (SEQ - 1))) * DIM;
        const float* ot1 = outputs_table + ((size_t)pid * SEQ + (gr1 & (SEQ - 1))) * DIM;
#pragma unroll
        for (int j = 0; j < 4; j++) {
            int col = n0 + wn * 32 + j * 8 + (lane & 3) * 2;
            float c0 = acc[i][j][0], c1 = acc[i][j][1];
            float c2 = acc[i][j][2], c3 = acc[i][j][3];
            float o0 = init ? ot0[col] : c0;
            float o1 = init ? ot0[col + 1] : c1;
            float o2 = init ? ot1[col] : c2;
            float o3 = init ? ot1[col + 1] : c3;
            float2 v0 = make_float2(c0 - simn0 * co2[j].x + sig0 * o0,
                                    c1 - simn0 * co2[j].y + sig0 * o1);
            float2 v1 = make_float2(c2 - simn1 * co2[j].x + sig1 * o2,
                                    c3 - simn1 * co2[j].y + sig1 * o3);
            *(float2*)&out[(size_t)gr0 * DIM + col] = v0;
            *(float2*)&out[(size_t)gr1 * DIM + col] = v1;
        }
    }
}

// --------------------------------- launch ---------------------------------------
extern "C" void kernel_launch(void* const* d_in, const int* in_sizes, int n_in,
                              void* d_out, int out_size) {
    const int*     prompt_ids      = (const int*)d_in[0];
    const float*   text_enc        = (const float*)d_in[1];
    const int*     concept_indices = (const int*)d_in[2];
    const float*   weight          = (const float*)d_in[3];
    const float*   C_inv           = (const float*)d_in[4];
    const uint8_t* initted         = (const uint8_t*)d_in[5];
    const float*   ema_table       = (const float*)d_in[6];
    const float*   outputs_table   = (const float*)d_in[7];
    float*         out             = (float*)d_out;

    (void)in_sizes; (void)n_in; (void)out_size;

    cudaFuncSetAttribute(k_main, cudaFuncAttributeMaxDynamicSharedMemorySize, SMEM_TOTAL);

    k_p1<<<1024 + 256, 128>>>(weight, C_inv, prompt_ids, concept_indices,
                              initted, ema_table, text_enc);
    k_p2<<<2048 + 128, 256>>>(prompt_ids, concept_indices, initted,
                              ema_table, text_enc);
    k_main<<<dim3(DIM / BN, (BATCH * SEQ) / BM), 256, SMEM_TOTAL>>>(
        prompt_ids, initted, outputs_table, out);
}

// round 17
// speedup vs baseline: 1.3063x; 1.3063x over previous
#include <cuda_runtime.h>
#include <cuda_fp16.h>
#include <stdint.h>
#include <math.h>

#define BATCH 64
#define SEQ   256
#define DIM   1024
#define BETA_C 0.75f
#define TEMP_C 0.1f

// ---- GEMM tiling ----
#define BM 128
#define BN 128
#define BK 32
#define NKT (DIM / BK)              // 32 k-chunks
#define STAGES 4
#define STAGE_BYTES 16384           // A 8KB + B 8KB (halves)
#define SMEM_TOTAL (STAGES * STAGE_BYTES)   // 64 KB

// ---------------- device scratch ----------------
__device__ float g_part[2][4][BATCH][DIM];   // split-K partials: [iCi|co][ks][b][d]
__device__ float g_simn[BATCH * SEQ];
__device__ float g_sig[BATCH * SEQ];
__device__ __half g_Ah[BATCH * SEQ * DIM];   // text_enc in fp16
__device__ __half g_Wh[DIM * DIM];           // weight in fp16

// ========== K1: split-K small GEMMs + Wh convert (uniform-duration blocks) ======
// grid (8, 8, 9), 128 threads.
//   z 0..3 : iCi partials  (M = Cinv, direct rows — R9-exact body)
//   z 4..7 : co  partials  (M = W, in-block 128x32 smem transpose)
//   z == 8 : Wh fp16 convert (x,y select 1/64 slice)
__global__ __launch_bounds__(128) void k_smallgemm(
    const float* __restrict__ W,
    const float* __restrict__ Cinv,
    const int* __restrict__ prompt_ids,
    const int* __restrict__ concept_indices,
    const uint8_t* __restrict__ initted,
    const float* __restrict__ ema_table,
    const float* __restrict__ text_enc) {
    __shared__ const float* srcp[8];
    __shared__ float ish[8][128];
    __shared__ float wtT[32][129];

    const int tx = threadIdx.x;
    const int z = blockIdx.z;

    if (z == 8) {
        // ---- Wh convert: 64 blocks x 128 thr x 16 iters x 8 elems = 1,048,576 ----
        size_t base = ((size_t)(blockIdx.y * 8 + blockIdx.x) * 128 + tx) * 8;
#pragma unroll
        for (int it = 0; it < 16; it++) {
            size_t i = base + (size_t)it * 65536;
            float4 v0 = *(const float4*)(W + i);
            float4 v1 = *(const float4*)(W + i + 4);
            __half2 h[4] = {__floats2half2_rn(v0.x, v0.y), __floats2half2_rn(v0.z, v0.w),
                            __floats2half2_rn(v1.x, v1.y), __floats2half2_rn(v1.z, v1.w)};
            *(uint4*)(g_Wh + i) = *(uint4*)h;
        }
        return;
    }

    const int d0 = blockIdx.x * 128;
    const int d = d0 + tx;
    const int b0 = blockIdx.y * 8;
    const int zz = z >> 2;                    // 0: iCi, 1: co
    const int ks = z & 3;

    if (tx < 8) {
        int b = b0 + tx;
        int pid = prompt_ids[b];
        int ci = concept_indices[b];
        bool init = initted[pid] != 0;
        srcp[tx] = init ? (ema_table + (size_t)pid * DIM)
                        : (text_enc + ((size_t)b * SEQ + ci) * DIM);
    }
    __syncthreads();

    float acc[8];
#pragma unroll
    for (int r = 0; r < 8; r++) acc[r] = 0.0f;

    const int kbase = ks * 256;

    if (zz == 0) {
        // ---- iCi: Cinv rows are directly coalesced (R9-exact) ----
#pragma unroll
        for (int kh = 0; kh < 2; kh++) {
            int k0 = kbase + kh * 128;
#pragma unroll
            for (int r = 0; r < 8; r++) ish[r][tx] = srcp[r][k0 + tx];
            __syncthreads();
#pragma unroll 4
            for (int kk = 0; kk < 128; kk++) {
                float m = Cinv[(size_t)(k0 + kk) * DIM + d];
#pragma unroll
                for (int r = 0; r < 8; r++) acc[r] += ish[r][kk] * m;
            }
            __syncthreads();
        }
#pragma unroll
        for (int r = 0; r < 8; r++) g_part[0][ks][b0 + r][d] = acc[r];
    } else {
        // ---- co: read W[d][k] via in-block 128x32 transpose tiles ----
        const int lane = tx & 31, wrow = tx >> 5;   // 4 warps
#pragma unroll
        for (int kh = 0; kh < 2; kh++) {
            int k0 = kbase + kh * 128;
#pragma unroll
            for (int r = 0; r < 8; r++) ish[r][tx] = srcp[r][k0 + tx];
            __syncthreads();
#pragma unroll
            for (int kc = 0; kc < 4; kc++) {
                int kk0 = k0 + kc * 32;
                // load W tile rows d0..d0+127, cols kk0..kk0+31, transposed
#pragma unroll
                for (int rr = wrow; rr < 128; rr += 4)
                    wtT[lane][rr] = W[(size_t)(d0 + rr) * DIM + kk0 + lane];
                __syncthreads();
#pragma unroll 4
                for (int kk = 0; kk < 32; kk++) {
                    float m = wtT[kk][tx];
#pragma unroll
                    for (int r = 0; r < 8; r++) acc[r] += ish[r][kc * 32 + kk] * m;
                }
                __syncthreads();
            }
        }
#pragma unroll
        for (int r = 0; r < 8; r++) g_part[1][ks][b0 + r][d] = acc[r];
    }
}

// ---------------- K2: fused iCi-reduce + energy + sim/sigmoid + A fp16 (R9 exact)
__global__ __launch_bounds__(256) void k_simE(
    const int* __restrict__ prompt_ids,
    const int* __restrict__ concept_indices,
    const uint8_t* __restrict__ initted,
    const float* __restrict__ ema_table,
    const float* __restrict__ text_enc) {
    __shared__ float sm_iCi[DIM];
    __shared__ float red[8];
    __shared__ float sE;

    const int tid = threadIdx.x;
    const int m0 = blockIdx.x * 8;
    const int b = blockIdx.x >> 5;

    int pid = prompt_ids[b];
    int ci = concept_indices[b];
    bool init = initted[pid] != 0;
    const float* isrc = init ? (ema_table + (size_t)pid * DIM)
                             : (text_enc + ((size_t)b * SEQ + ci) * DIM);

    float s = 0.0f;
    for (int d = tid; d < DIM; d += 256) {
        float v = g_part[0][0][b][d] + g_part[0][1][b][d] +
                  g_part[0][2][b][d] + g_part[0][3][b][d];
        sm_iCi[d] = v;
        s += v * isrc[d];
    }
#pragma unroll
    for (int o = 16; o; o >>= 1) s += __shfl_xor_sync(0xffffffffu, s, o);
    if ((tid & 31) == 0) red[tid >> 5] = s;
    __syncthreads();
    if (tid == 0) {
        float t = 0.0f;
#pragma unroll
        for (int w = 0; w < 8; w++) t += red[w];
        sE = t;
    }
    __syncthreads();

    const int wr = tid >> 5, lane = tid & 31;
    const int m = m0 + wr;
    const float4* x = (const float4*)(text_enc + (size_t)m * DIM);
    const float4* c4 = (const float4*)sm_iCi;
    __half* arow = g_Ah + (size_t)m * DIM;
    float dot = 0.0f;
#pragma unroll
    for (int it = 0; it < 8; it++) {
        int idx = it * 32 + lane;
        float4 xv = x[idx];
        float4 cv = c4[idx];
        dot += xv.x * cv.x + xv.y * cv.y + xv.z * cv.z + xv.w * cv.w;
        __half2 h0 = __floats2half2_rn(xv.x, xv.y);
        __half2 h1 = __floats2half2_rn(xv.z, xv.w);
        uint2 h;
        h.x = *(uint32_t*)&h0;
        h.y = *(uint32_t*)&h1;
        *(uint2*)(arow + idx * 4) = h;
    }
#pragma unroll
    for (int o = 16; o; o >>= 1) dot += __shfl_xor_sync(0xffffffffu, dot, o);
    if (lane == 0) {
        float simn = dot / sE;
        g_simn[m] = simn;
        g_sig[m] = 1.0f / (1.0f + expf(-(simn - BETA_C) / TEMP_C));
    }
}

// ---------------- PTX helpers ----------------
__device__ __forceinline__ uint32_t smem_u32(const void* p) {
    uint32_t a;
    asm("{ .reg .u64 t; cvta.to.shared.u64 t, %1; cvt.u32.u64 %0, t; }" : "=r"(a) : "l"(p));
    return a;
}
__device__ __forceinline__ void cp16(uint32_t dst, const void* src) {
    asm volatile("cp.async.cg.shared.global [%0], [%1], 16;" :: "r"(dst), "l"(src) : "memory");
}
#define CP_COMMIT() asm volatile("cp.async.commit_group;" ::: "memory")
#define CP_WAIT2()  asm volatile("cp.async.wait_group 2;" ::: "memory")
__device__ __forceinline__ uint4 ldsm4(uint32_t addr) {
    uint4 v;
    asm volatile("ldmatrix.sync.aligned.m8n8.x4.shared.b16 {%0,%1,%2,%3}, [%4];"
                 : "=r"(v.x), "=r"(v.y), "=r"(v.z), "=r"(v.w) : "r"(addr));
    return v;
}
__device__ __forceinline__ void mma_f16(float* c, const uint4& a, uint32_t b0, uint32_t b1) {
    asm volatile(
        "mma.sync.aligned.m16n8k16.row.col.f32.f16.f16.f32 "
        "{%0,%1,%2,%3}, {%4,%5,%6,%7}, {%8,%9}, {%0,%1,%2,%3};"
        : "+f"(c[0]), "+f"(c[1]), "+f"(c[2]), "+f"(c[3])
        : "r"(a.x), "r"(a.y), "r"(a.z), "r"(a.w), "r"(b0), "r"(b1));
}
// physical byte offset of (row, 16B-chunk c) in an 8KB half-tile [128 rows x 64B], swizzled
__device__ __forceinline__ uint32_t phys(int r, int c) {
    uint32_t line = r >> 1;
    uint32_t u = ((r & 1) << 2) | c;
    return line * 128 + ((u ^ (line & 7)) << 4);
}

// ---------------- K3: fp16 cp.async + ldmatrix GEMM + fused epilogue (R9 exact) ----
__global__ __launch_bounds__(256, 2) void k_main(
    const int* __restrict__ prompt_ids,
    const uint8_t* __restrict__ initted,
    const float* __restrict__ outputs_table,  // [512][256][1024]
    float* __restrict__ out) {
    extern __shared__ char smem[];
    const uint32_t sb = smem_u32(smem);

    const int tid = threadIdx.x;
    const int wid = tid >> 5, lane = tid & 31;
    const int wm = wid & 1, wn = wid >> 1;     // warp tile rows 64*wm, cols 32*wn
    const int m0 = blockIdx.y * BM;
    const int n0 = blockIdx.x * BN;

    // ---- producer mapping: 2 A chunks + 2 B chunks per thread per stage ----
    const int chA0 = tid, chA1 = tid + 256;    // 0..511
    const int rA0 = chA0 >> 2, cA0 = chA0 & 3;
    const int rA1 = chA1 >> 2, cA1 = chA1 & 3;
    const __half* srcA0 = g_Ah + (size_t)(m0 + rA0) * DIM + cA0 * 8;
    const __half* srcA1 = g_Ah + (size_t)(m0 + rA1) * DIM + cA1 * 8;
    const __half* srcB0 = g_Wh + (size_t)(n0 + rA0) * DIM + cA0 * 8;
    const __half* srcB1 = g_Wh + (size_t)(n0 + rA1) * DIM + cA1 * 8;
    const uint32_t dA0 = phys(rA0, cA0), dA1 = phys(rA1, cA1);
    const uint32_t dB0 = 8192 + dA0, dB1 = 8192 + dA1;

    // ---- consumer ldmatrix offsets ----
    const int lane15 = lane & 15, lanehi = lane >> 4;
    uint32_t offA[4][2], offB[2][2];
#pragma unroll
    for (int i = 0; i < 4; i++)
#pragma unroll
        for (int ks = 0; ks < 2; ks++)
            offA[i][ks] = phys(wm * 64 + i * 16 + lane15, ks * 2 + lanehi);
#pragma unroll
    for (int j2 = 0; j2 < 2; j2++)
#pragma unroll
        for (int ks = 0; ks < 2; ks++)
            offB[j2][ks] = 8192 + phys(wn * 32 + j2 * 16 + lane15, ks * 2 + lanehi);

    float acc[4][4][4];
#pragma unroll
    for (int i = 0; i < 4; i++)
#pragma unroll
        for (int j = 0; j < 4; j++)
#pragma unroll
            for (int r = 0; r < 4; r++) acc[i][j][r] = 0.0f;

    // ---- prologue: issue stages 0..2 ----
#pragma unroll
    for (int s = 0; s < 3; s++) {
        uint32_t base = sb + s * STAGE_BYTES;
        int ko = s * BK;
        cp16(base + dA0, srcA0 + ko);
        cp16(base + dA1, srcA1 + ko);
        cp16(base + dB0, srcB0 + ko);
        cp16(base + dB1, srcB1 + ko);
        CP_COMMIT();
    }

    for (int kt = 0; kt < NKT; kt++) {
        CP_WAIT2();
        __syncthreads();
        uint32_t base = sb + (kt & (STAGES - 1)) * STAGE_BYTES;
#pragma unroll
        for (int ks = 0; ks < 2; ks++) {
            uint4 af[4], bf[2];
#pragma unroll
            for (int i = 0; i < 4; i++) af[i] = ldsm4(base + offA[i][ks]);
#pragma unroll
            for (int j2 = 0; j2 < 2; j2++) bf[j2] = ldsm4(base + offB[j2][ks]);
#pragma unroll
            for (int i = 0; i < 4; i++) {
                mma_f16(acc[i][0], af[i], bf[0].x, bf[0].z);
                mma_f16(acc[i][1], af[i], bf[0].y, bf[0].w);
                mma_f16(acc[i][2], af[i], bf[1].x, bf[1].z);
                mma_f16(acc[i][3], af[i], bf[1].y, bf[1].w);
            }
        }
        if (kt + 3 < NKT) {
            uint32_t nb = sb + ((kt + 3) & (STAGES - 1)) * STAGE_BYTES;
            int ko = (kt + 3) * BK;
            cp16(nb + dA0, srcA0 + ko);
            cp16(nb + dA1, srcA1 + ko);
            cp16(nb + dB0, srcB0 + ko);
            cp16(nb + dB1, srcB1 + ko);
        }
        CP_COMMIT();
    }

    // ---------------- fused epilogue ----------------
    const int b = m0 >> 8;
    const int pid = prompt_ids[b];
    const bool init = initted[pid] != 0;

    float2 co2[4];
#pragma unroll
    for (int j = 0; j < 4; j++) {
        int col = n0 + wn * 32 + j * 8 + (lane & 3) * 2;
        float2 v = *(const float2*)&g_part[1][0][b][col];
        float2 v1 = *(const float2*)&g_part[1][1][b][col];
        float2 v2 = *(const float2*)&g_part[1][2][b][col];
        float2 v3 = *(const float2*)&g_part[1][3][b][col];
        co2[j] = make_float2(v.x + v1.x + v2.x + v3.x, v.y + v1.y + v2.y + v3.y);
    }

#pragma unroll
    for (int i = 0; i < 4; i++) {
        int gr0 = m0 + wm * 64 + i * 16 + (lane >> 2);
        int gr1 = gr0 + 8;
        float simn0 = g_simn[gr0], sig0 = g_sig[gr0];
        float simn1 = g_simn[gr1], sig1 = g_sig[gr1];
        const float* ot0 = outputs_table + ((size_t)pid * SEQ + (gr0 & (SEQ - 1))) * DIM;
        const float* ot1 = outputs_table + ((size_t)pid * SEQ + (gr1 & (SEQ - 1))) * DIM;
#pragma unroll
        for (int j = 0; j < 4; j++) {
            int col = n0 + wn * 32 + j * 8 + (lane & 3) * 2;
            float c0 = acc[i][j][0], c1 = acc[i][j][1];
            float c2 = acc[i][j][2], c3 = acc[i][j][3];
            float o0 = init ? ot0[col] : c0;
            float o1 = init ? ot0[col + 1] : c1;
            float o2 = init ? ot1[col] : c2;
            float o3 = init ? ot1[col + 1] : c3;
            float2 v0 = make_float2(c0 - simn0 * co2[j].x + sig0 * o0,
                                    c1 - simn0 * co2[j].y + sig0 * o1);
            float2 v1 = make_float2(c2 - simn1 * co2[j].x + sig1 * o2,
                                    c3 - simn1 * co2[j].y + sig1 * o3);
            *(float2*)&out[(size_t)gr0 * DIM + col] = v0;
            *(float2*)&out[(size_t)gr1 * DIM + col] = v1;
        }
    }
}

// --------------------------------- launch ---------------------------------------
extern "C" void kernel_launch(void* const* d_in, const int* in_sizes, int n_in,
                              void* d_out, int out_size) {
    const int*     prompt_ids      = (const int*)d_in[0];
    const float*   text_enc        = (const float*)d_in[1];
    const int*     concept_indices = (const int*)d_in[2];
    const float*   weight          = (const float*)d_in[3];
    const float*   C_inv           = (const float*)d_in[4];
    const uint8_t* initted         = (const uint8_t*)d_in[5];
    const float*   ema_table       = (const float*)d_in[6];
    const float*   outputs_table   = (const float*)d_in[7];
    float*         out             = (float*)d_out;

    (void)in_sizes; (void)n_in; (void)out_size;

    cudaFuncSetAttribute(k_main, cudaFuncAttributeMaxDynamicSharedMemorySize, SMEM_TOTAL);

    k_smallgemm<<<dim3(8, 8, 9), 128>>>(weight, C_inv, prompt_ids, concept_indices,
                                        initted, ema_table, text_enc);
    k_simE<<<(BATCH * SEQ) / 8, 256>>>(prompt_ids, concept_indices, initted,
                                       ema_table, text_enc);
    k_main<<<dim3(DIM / BN, (BATCH * SEQ) / BM), 256, SMEM_TOTAL>>>(
        prompt_ids, initted, outputs_table, out);
}